// round 13
// baseline (speedup 1.0000x reference)
#include <cuda_runtime.h>
#include <cstdint>

#define BB   8
#define NN   128
#define COOR 3
#define FF   128
#define FILT 128

// Scratch: A' = x @ w1 + bv  and  C = x @ w2, each [B, N, COOR, FILT]
__device__ float g_A[BB * NN * COOR * FILT];
__device__ float g_C[BB * NN * COOR * FILT];

// ---- packed f32x2 helpers (phase 1 only) ----------------------------------
typedef unsigned long long ull;

union F2U {
    float2 f2;
    ull    u;
};

__device__ __forceinline__ ull fma2(ull a, ull b, ull c) {
    ull r;
    asm("fma.rn.f32x2 %0, %1, %2, %3;" : "=l"(r) : "l"(a), "l"(b), "l"(c));
    return r;
}
__device__ __forceinline__ ull pack2(float lo, float hi) {
    ull r;
    asm("mov.b64 %0, {%1, %2};" : "=l"(r) : "r"(__float_as_uint(lo)), "r"(__float_as_uint(hi)));
    return r;
}

__device__ __forceinline__ unsigned int smem_u32(const void* p) {
    unsigned int a;
    asm("{ .reg .u64 t; cvta.to.shared.u64 t, %1; cvt.u32.u64 %0, t; }"
        : "=r"(a) : "l"(p));
    return a;
}

// ---------------------------------------------------------------------------
// Phase 1 — R7 configuration VERBATIM (best measured across 6 designs).
// ---------------------------------------------------------------------------
__global__ __launch_bounds__(128) void phase1_kernel(
    const float* __restrict__ x,   // [3072, 128]
    const float* __restrict__ w,   // [256, 128]
    const float* __restrict__ bv)  // [128]
{
    constexpr int RT    = 8;
    constexpr int DEPTH = 8;
    const int r0   = blockIdx.x * RT;
    const int kh   = blockIdx.y * 64;
    const int warp = threadIdx.x >> 5;
    const int lane = threadIdx.x & 31;
    const int k    = kh + lane * 2;
    const int wr   = warp * 2;

    __shared__ float xs[RT][FF];

    {
        const float4* xin = reinterpret_cast<const float4*>(x + (size_t)r0 * FF);
        float4* xs4 = reinterpret_cast<float4*>(&xs[0][0]);
        #pragma unroll
        for (int t = threadIdx.x; t < RT * FF / 4; t += 128) xs4[t] = xin[t];
    }
    __syncthreads();

    ull acc[2][2];
    {
        const float2 b2 = *reinterpret_cast<const float2*>(bv + k);
        const ull bp = pack2(b2.x, b2.y);
        acc[0][0] = bp; acc[0][1] = 0ull;
        acc[1][0] = bp; acc[1][1] = 0ull;
    }

    const float* w1base = w + k;
    const float* w2base = w + (size_t)FF * FILT + k;

    F2U W1[DEPTH], W2[DEPTH];
    #pragma unroll
    for (int d = 0; d < DEPTH; d++) {
        W1[d].f2 = *reinterpret_cast<const float2*>(w1base + (size_t)d * FILT);
        W2[d].f2 = *reinterpret_cast<const float2*>(w2base + (size_t)d * FILT);
    }

    #pragma unroll 8
    for (int f = 0; f < FF; f++) {
        const int slot = f % DEPTH;

        const float xv0 = xs[wr + 0][f];
        const float xv1 = xs[wr + 1][f];
        const ull xp0 = pack2(xv0, xv0);
        const ull xp1 = pack2(xv1, xv1);

        const ull w1v = W1[slot].u;
        const ull w2v = W2[slot].u;

        acc[0][0] = fma2(xp0, w1v, acc[0][0]);
        acc[0][1] = fma2(xp0, w2v, acc[0][1]);
        acc[1][0] = fma2(xp1, w1v, acc[1][0]);
        acc[1][1] = fma2(xp1, w2v, acc[1][1]);

        if (f + DEPTH < FF) {
            W1[slot].f2 = *reinterpret_cast<const float2*>(w1base + (size_t)(f + DEPTH) * FILT);
            W2[slot].f2 = *reinterpret_cast<const float2*>(w2base + (size_t)(f + DEPTH) * FILT);
        }
    }

    #pragma unroll
    for (int r = 0; r < 2; r++) {
        const size_t row = (size_t)(r0 + wr + r);
        F2U oa; oa.u = acc[r][0];
        F2U oc; oc.u = acc[r][1];
        *reinterpret_cast<float2*>(&g_A[row * FILT + k]) = oa.f2;
        *reinterpret_cast<float2*>(&g_C[row * FILT + k]) = oc.f2;
    }
}

// ---------------------------------------------------------------------------
// Phase 2: out[b,i,j,k] = sum_c (A'[b,i,c,k] + C[b,j,c,k]) * d[b,i,j,c]
// R4 skeleton (TI=4, 256 blocks, scalar FMA, 1-ahead C prefetch), but the
// output path is moved OFF the LSU: STG.128 costs 12 issue-cyc each
// (~5.6us/SM of pure store-issue — the invariant binder that defeated
// prefetch/MLP/occupancy). Instead: STS.128 into a double-buffered 16KB
// stage, then 4x cp.async.bulk (4KB each, contiguous) per j-chunk via the
// TMA engine. bulk_group discipline: wait_group 1 keeps one chunk in
// flight; buffer reused 2 iterations later.
// ---------------------------------------------------------------------------
__global__ __launch_bounds__(256) void phase2_kernel(
    const float* __restrict__ dist,  // [B, N, N, COOR]
    float* __restrict__ out)         // [B, N, N, FILT]
{
    constexpr int TI = 4;
    const int b  = blockIdx.y;
    const int i0 = blockIdx.x * TI;
    const int tx = threadIdx.x;   // 0..31
    const int ty = threadIdx.y;   // 0..7
    const int tid = ty * 32 + tx;

    __shared__ float4 sd4[TI * NN];            // padded dist: 8 KB
    __shared__ float4 stage[2][TI * 8 * 32];   // 2 x 16 KB output staging

    // Load + pad distances slice d[b, i0:i0+4, :, :].
    {
        const float* dbase = dist + (size_t)(b * NN + i0) * NN * COOR;
        #pragma unroll
        for (int t = tid; t < TI * NN; t += 256) {
            const int e = t * COOR;
            sd4[t] = make_float4(dbase[e], dbase[e + 1], dbase[e + 2], 0.0f);
        }
    }

    // A' tile into registers: 4 i x 3 c x float4 = 48 regs.
    float4 Ar[TI][COOR];
    {
        const float4* A4 = reinterpret_cast<const float4*>(g_A);
        #pragma unroll
        for (int i = 0; i < TI; i++)
            #pragma unroll
            for (int c = 0; c < COOR; c++)
                Ar[i][c] = A4[((size_t)(b * NN + i0 + i) * COOR + c) * (FILT / 4) + tx];
    }
    __syncthreads();

    const float4* C4 = reinterpret_cast<const float4*>(g_C) +
                       (size_t)b * NN * COOR * (FILT / 4) + tx;
    float* const outBase = out + ((size_t)(b * NN + i0) * NN) * FILT;

    // Prime C pipeline with j = ty.
    float4 c0 = C4[(size_t)ty * COOR * (FILT / 4) + 0 * (FILT / 4)];
    float4 c1 = C4[(size_t)ty * COOR * (FILT / 4) + 1 * (FILT / 4)];
    float4 c2 = C4[(size_t)ty * COOR * (FILT / 4) + 2 * (FILT / 4)];

    int buf = 0;

    for (int it = 0; it < NN / 8; it++) {
        const int j = ty + it * 8;

        float4 n0, n1, n2;
        if (it + 1 < NN / 8) {
            const size_t nb = (size_t)(j + 8) * COOR * (FILT / 4);
            n0 = C4[nb + 0 * (FILT / 4)];
            n1 = C4[nb + 1 * (FILT / 4)];
            n2 = C4[nb + 2 * (FILT / 4)];
        }

        // Compute and stage via STS.128 (cheap issue) instead of STG.128.
        #pragma unroll
        for (int i = 0; i < TI; i++) {
            const float4 dv = sd4[i * NN + j];   // broadcast LDS.128
            const float d0 = dv.x, d1 = dv.y, d2 = dv.z;

            float4 o;
            o.x = fmaf(Ar[i][0].x + c0.x, d0,
                  fmaf(Ar[i][1].x + c1.x, d1, (Ar[i][2].x + c2.x) * d2));
            o.y = fmaf(Ar[i][0].y + c0.y, d0,
                  fmaf(Ar[i][1].y + c1.y, d1, (Ar[i][2].y + c2.y) * d2));
            o.z = fmaf(Ar[i][0].z + c0.z, d0,
                  fmaf(Ar[i][1].z + c1.z, d1, (Ar[i][2].z + c2.z) * d2));
            o.w = fmaf(Ar[i][0].w + c0.w, d0,
                  fmaf(Ar[i][1].w + c1.w, d1, (Ar[i][2].w + c2.w) * d2));

            stage[buf][(i * 8 + ty) * 32 + tx] = o;
        }

        c0 = n0; c1 = n1; c2 = n2;

        __syncthreads();   // stage[buf] fully written

        // 4 threads (tid 0..3) each push one contiguous 4KB row-chunk:
        // out[b, i0+i, it*8 : it*8+8, :]  (8*128 floats, contiguous).
        if (tid < TI) {
            asm volatile("fence.proxy.async;" ::: "memory");
            const unsigned int src = smem_u32(&stage[buf][tid * 8 * 32]);
            float* dst = outBase + ((size_t)tid * NN + it * 8) * FILT;
            asm volatile(
                "cp.async.bulk.global.shared::cta.bulk_group [%0], [%1], %2;"
                :: "l"(dst), "r"(src), "r"(8 * FILT * 4) : "memory");
            asm volatile("cp.async.bulk.commit_group;" ::: "memory");
            // Keep at most 1 group (this one) in flight -> the buffer used
            // two iterations ago is guaranteed drained.
            asm volatile("cp.async.bulk.wait_group 1;" ::: "memory");
        }
        __syncthreads();   // all threads see: other buffer is reusable

        buf ^= 1;
    }

    // Drain outstanding TMA stores before kernel exit.
    if (tid < TI) {
        asm volatile("cp.async.bulk.wait_group 0;" ::: "memory");
    }
}

extern "C" void kernel_launch(void* const* d_in, const int* in_sizes, int n_in,
                              void* d_out, int out_size)
{
    const float* x    = (const float*)d_in[0];  // vector_features [8,128,3,128]
    const float* dist = (const float*)d_in[1];  // distances       [8,128,128,3]
    const float* w    = (const float*)d_in[2];  // w_vs            [256,128]
    const float* bv   = (const float*)d_in[3];  // b_vs            [128]
    float* out = (float*)d_out;                 // [8,128,128,128]

    (void)in_sizes; (void)n_in; (void)out_size;

    phase1_kernel<<<dim3((BB * NN * COOR) / 8, 2), 128>>>(x, w, bv);
    phase2_kernel<<<dim3(NN / 4, BB), dim3(32, 8)>>>(dist, out);
}

// round 14
// speedup vs baseline: 1.2347x; 1.2347x over previous
#include <cuda_runtime.h>
#include <cstdint>

#define BB   8
#define NN   128
#define COOR 3
#define FF   128
#define FILT 128

// Scratch: A' = x @ w1 + bv  and  C = x @ w2, each [B, N, COOR, FILT]
__device__ float g_A[BB * NN * COOR * FILT];
__device__ float g_C[BB * NN * COOR * FILT];

// ---- packed f32x2 helpers (phase 1 only) ----------------------------------
typedef unsigned long long ull;

union F4U {
    float4 f4;
    ull    u[2];
};
union F2U {
    float2 f2;
    ull    u;
};

__device__ __forceinline__ ull fma2(ull a, ull b, ull c) {
    ull r;
    asm("fma.rn.f32x2 %0, %1, %2, %3;" : "=l"(r) : "l"(a), "l"(b), "l"(c));
    return r;
}
__device__ __forceinline__ ull pack2(float lo, float hi) {
    ull r;
    asm("mov.b64 %0, {%1, %2};" : "=l"(r) : "r"(__float_as_uint(lo)), "r"(__float_as_uint(hi)));
    return r;
}

// ---------------------------------------------------------------------------
// Phase 1: tiny GEMM [3072, 128] @ [128, 256]  ->  g_A (with +bv), g_C
// LSU-op-count model (validated: R7 = 393K warp-iters x 4 LSU ops ~ 11us):
// lane now owns a k-QUAD (2x LDG.128/f covers all 128 k per warp), halving
// chip warp-iters to 196K at the same 4 LSU ops each -> predict ~6us.
// 2 rows/warp, 8 rows/block, grid 384 (10.4 warps/SM), DEPTH-8 float4
// w-prefetch (covers L2 latency), x pre-packed as (x,x) f32x2 in smem
// (LDS.64 broadcast, zero pack MOVs in the loop).
// ---------------------------------------------------------------------------
__global__ __launch_bounds__(128) void phase1_kernel(
    const float* __restrict__ x,   // [3072, 128]
    const float* __restrict__ w,   // [256, 128]
    const float* __restrict__ bv)  // [128]
{
    constexpr int RT    = 8;             // rows per block
    constexpr int DEPTH = 8;             // w-prefetch pipeline depth
    const int r0   = blockIdx.x * RT;
    const int warp = threadIdx.x >> 5;   // 0..3
    const int lane = threadIdx.x & 31;
    const int k    = lane * 4;           // this thread's k-quad (covers 128k/warp)
    const int wr   = warp * 2;           // first of this warp's 2 rows

    __shared__ ull xs2[RT * FF];         // pre-packed (x,x) pairs: 8 KB

    // Stage x-tile pre-duplicated: xs2[row*128 + f] = (x, x).
    {
        const float4* xin = reinterpret_cast<const float4*>(x + (size_t)r0 * FF);
        #pragma unroll
        for (int t = threadIdx.x; t < RT * FF / 4; t += 128) {
            const float4 v = xin[t];
            ulonglong2* dst = reinterpret_cast<ulonglong2*>(&xs2[4 * t]);
            dst[0] = make_ulonglong2(pack2(v.x, v.x), pack2(v.y, v.y));
            dst[1] = make_ulonglong2(pack2(v.z, v.z), pack2(v.w, v.w));
        }
    }
    __syncthreads();

    // acc[row][A/C][pair]  (each pair = 2 k-values)
    ull acc[2][2][2];
    {
        F4U bq;
        bq.f4 = *reinterpret_cast<const float4*>(bv + k);
        #pragma unroll
        for (int r = 0; r < 2; r++) {
            acc[r][0][0] = bq.u[0];  acc[r][0][1] = bq.u[1];
            acc[r][1][0] = 0ull;     acc[r][1][1] = 0ull;
        }
    }

    const float4* w1p = reinterpret_cast<const float4*>(w) + lane;
    const float4* w2p = reinterpret_cast<const float4*>(w + (size_t)FF * FILT) + lane;

    // Prime the depth-8 rotating pipeline (float4 = full k-quad per slot).
    F4U W1[DEPTH], W2[DEPTH];
    #pragma unroll
    for (int d = 0; d < DEPTH; d++) {
        W1[d].f4 = w1p[d * (FILT / 4)];
        W2[d].f4 = w2p[d * (FILT / 4)];
    }

    const ull* xrow = &xs2[wr * FF];

    #pragma unroll 8   // = DEPTH, so f % DEPTH is a compile-time slot index
    for (int f = 0; f < FF; f++) {
        const int slot = f % DEPTH;

        const ull xp0 = xrow[f];            // LDS.64 broadcast, pre-packed
        const ull xp1 = xrow[FF + f];

        acc[0][0][0] = fma2(xp0, W1[slot].u[0], acc[0][0][0]);
        acc[0][0][1] = fma2(xp0, W1[slot].u[1], acc[0][0][1]);
        acc[0][1][0] = fma2(xp0, W2[slot].u[0], acc[0][1][0]);
        acc[0][1][1] = fma2(xp0, W2[slot].u[1], acc[0][1][1]);
        acc[1][0][0] = fma2(xp1, W1[slot].u[0], acc[1][0][0]);
        acc[1][0][1] = fma2(xp1, W1[slot].u[1], acc[1][0][1]);
        acc[1][1][0] = fma2(xp1, W2[slot].u[0], acc[1][1][0]);
        acc[1][1][1] = fma2(xp1, W2[slot].u[1], acc[1][1][1]);

        // Refill this slot for iteration f + DEPTH.
        if (f + DEPTH < FF) {
            W1[slot].f4 = w1p[(f + DEPTH) * (FILT / 4)];
            W2[slot].f4 = w2p[(f + DEPTH) * (FILT / 4)];
        }
    }

    #pragma unroll
    for (int r = 0; r < 2; r++) {
        const size_t row = (size_t)(r0 + wr + r);
        F4U oa; oa.u[0] = acc[r][0][0]; oa.u[1] = acc[r][0][1];
        F4U oc; oc.u[0] = acc[r][1][0]; oc.u[1] = acc[r][1][1];
        *reinterpret_cast<float4*>(&g_A[row * FILT + k]) = oa.f4;
        *reinterpret_cast<float4*>(&g_C[row * FILT + k]) = oc.f4;
    }
}

// ---------------------------------------------------------------------------
// Phase 2 — R4 configuration VERBATIM (local optimum across 6 variants:
// 16.35us). 256 blocks single wave, block (32,8), TI=4, A' in registers,
// distances padded to float4 in smem, C loads prefetched 1 iter ahead,
// scalar FMA, STG.128 direct.
// ---------------------------------------------------------------------------
__global__ __launch_bounds__(256) void phase2_kernel(
    const float* __restrict__ dist,  // [B, N, N, COOR]
    float* __restrict__ out)         // [B, N, N, FILT]
{
    constexpr int TI = 4;
    const int b  = blockIdx.y;
    const int i0 = blockIdx.x * TI;
    const int tx = threadIdx.x;   // 0..31
    const int ty = threadIdx.y;   // 0..7
    const int tid = ty * 32 + tx;

    __shared__ float4 sd4[TI * NN];   // padded (d0,d1,d2,_) per (i,j): 8 KB

    {
        const float* dbase = dist + (size_t)(b * NN + i0) * NN * COOR;
        #pragma unroll
        for (int t = tid; t < TI * NN; t += 256) {
            const int e = t * COOR;
            sd4[t] = make_float4(dbase[e], dbase[e + 1], dbase[e + 2], 0.0f);
        }
    }

    float4 Ar[TI][COOR];
    {
        const float4* A4 = reinterpret_cast<const float4*>(g_A);
        #pragma unroll
        for (int i = 0; i < TI; i++)
            #pragma unroll
            for (int c = 0; c < COOR; c++)
                Ar[i][c] = A4[((size_t)(b * NN + i0 + i) * COOR + c) * (FILT / 4) + tx];
    }
    __syncthreads();

    const float4* C4 = reinterpret_cast<const float4*>(g_C) +
                       (size_t)b * NN * COOR * (FILT / 4) + tx;
    float4* out4 = reinterpret_cast<float4*>(out) +
                   ((size_t)(b * NN + i0) * NN) * (FILT / 4) + tx;

    float4 c0 = C4[(size_t)ty * COOR * (FILT / 4) + 0 * (FILT / 4)];
    float4 c1 = C4[(size_t)ty * COOR * (FILT / 4) + 1 * (FILT / 4)];
    float4 c2 = C4[(size_t)ty * COOR * (FILT / 4) + 2 * (FILT / 4)];

    #pragma unroll
    for (int it = 0; it < NN / 8; it++) {
        const int j = ty + it * 8;

        float4 n0, n1, n2;
        if (it + 1 < NN / 8) {
            const size_t nb = (size_t)(j + 8) * COOR * (FILT / 4);
            n0 = C4[nb + 0 * (FILT / 4)];
            n1 = C4[nb + 1 * (FILT / 4)];
            n2 = C4[nb + 2 * (FILT / 4)];
        }

        #pragma unroll
        for (int i = 0; i < TI; i++) {
            const float4 dv = sd4[i * NN + j];   // one LDS.128 broadcast
            const float d0 = dv.x, d1 = dv.y, d2 = dv.z;

            float4 o;
            o.x = fmaf(Ar[i][0].x + c0.x, d0,
                  fmaf(Ar[i][1].x + c1.x, d1, (Ar[i][2].x + c2.x) * d2));
            o.y = fmaf(Ar[i][0].y + c0.y, d0,
                  fmaf(Ar[i][1].y + c1.y, d1, (Ar[i][2].y + c2.y) * d2));
            o.z = fmaf(Ar[i][0].z + c0.z, d0,
                  fmaf(Ar[i][1].z + c1.z, d1, (Ar[i][2].z + c2.z) * d2));
            o.w = fmaf(Ar[i][0].w + c0.w, d0,
                  fmaf(Ar[i][1].w + c1.w, d1, (Ar[i][2].w + c2.w) * d2));

            out4[((size_t)i * NN + j) * (FILT / 4)] = o;
        }

        c0 = n0; c1 = n1; c2 = n2;
    }
}

extern "C" void kernel_launch(void* const* d_in, const int* in_sizes, int n_in,
                              void* d_out, int out_size)
{
    const float* x    = (const float*)d_in[0];  // vector_features [8,128,3,128]
    const float* dist = (const float*)d_in[1];  // distances       [8,128,128,3]
    const float* w    = (const float*)d_in[2];  // w_vs            [256,128]
    const float* bv   = (const float*)d_in[3];  // b_vs            [128]
    float* out = (float*)d_out;                 // [8,128,128,128]

    (void)in_sizes; (void)n_in; (void)out_size;

    phase1_kernel<<<(BB * NN * COOR) / 8, 128>>>(x, w, bv);
    phase2_kernel<<<dim3(NN / 4, BB), dim3(32, 8)>>>(dist, out);
}